// round 1
// baseline (speedup 1.0000x reference)
#include <cuda_runtime.h>

// BSplineLayer: piecewise-linear spline eval.
// u: [4096, 64, 256] f32 (flat N, channel = i % 256)
// knots: [256, 64] f32 sorted ascending per channel
// coefs: [256, 64] f32
// out[i] = c0 + (u[i]-k0)/(k1-k0+1e-6) * (c1-c0), segment by searchsorted-left.

#define M_CH    256
#define K_KNOTS 64
#define KP      65        // padded row stride: bank = (c + j) % 32, avoids j-only banking
#define EPS     1e-6f

#define SMEM_FLOATS (3 * M_CH * KP + M_CH)
#define SMEM_BYTES  (SMEM_FLOATS * (int)sizeof(float))

__global__ __launch_bounds__(1024, 1)
void bspline_kernel(const float* __restrict__ u,
                    const float* __restrict__ knots,
                    const float* __restrict__ coefs,
                    float* __restrict__ out,
                    int n4 /* number of float4 elements */)
{
    extern __shared__ float smem[];
    float* sk    = smem;                 // [M_CH][KP] knots
    float* sc    = sk  + M_CH * KP;      // [M_CH][KP] coefs
    float* sid   = sc  + M_CH * KP;      // [M_CH][KP] 1/(k[j+1]-k[j]+eps), j in [0,K-2]
    float* sinvh = sid + M_CH * KP;      // [M_CH]     (K-1)/(k_last-k_first)

    // ---- prologue: stage tables into shared ----
    for (int i = threadIdx.x; i < M_CH * K_KNOTS; i += blockDim.x) {
        int c = i >> 6;          // / 64
        int j = i & 63;          // % 64
        sk[c * KP + j] = knots[i];
        sc[c * KP + j] = coefs[i];
    }
    __syncthreads();
    for (int i = threadIdx.x; i < M_CH * (K_KNOTS - 1); i += blockDim.x) {
        int c = i / (K_KNOTS - 1);
        int j = i % (K_KNOTS - 1);
        float k0 = sk[c * KP + j];
        float k1 = sk[c * KP + j + 1];
        sid[c * KP + j] = 1.0f / (k1 - k0 + EPS);
    }
    for (int c = threadIdx.x; c < M_CH; c += blockDim.x) {
        float kf = sk[c * KP];
        float kl = sk[c * KP + K_KNOTS - 1];
        sinvh[c] = (float)(K_KNOTS - 1) / fmaxf(kl - kf, 1e-12f);
    }
    __syncthreads();

    const float4* __restrict__ u4 = (const float4*)u;
    float4*       __restrict__ o4 = (float4*)out;

    const int stride = blockDim.x * gridDim.x;
    const int tid    = blockIdx.x * blockDim.x + threadIdx.x;
    const int n8     = n4 >> 1;   // process two float4 per iteration

    for (int t = tid; t < n8; t += stride) {
        // issue both loads up-front for MLP
        float4 a = u4[2 * t];
        float4 b = u4[2 * t + 1];

        // element index of a.x is 8*t; 8 | 256 so 8 consecutive channels, no wrap
        const int cb = (t * 8) & (M_CH - 1);

        float x[8] = {a.x, a.y, a.z, a.w, b.x, b.y, b.z, b.w};
        float r[8];

        #pragma unroll
        for (int i = 0; i < 8; i++) {
            const int   c    = cb + i;
            const int   base = c * KP;
            const float xi   = x[i];

            // affine initial guess (exact for uniform knots), then exact fix-up
            int j = (int)floorf((xi - sk[base]) * sinvh[c]);
            j = min(max(j, 0), K_KNOTS - 2);
            // want: largest j with knots[j] < xi (clamped); searchsorted-left semantics
            while (j > 0 && sk[base + j] >= xi) --j;
            while (j < K_KNOTS - 2 && sk[base + j + 1] < xi) ++j;

            const float k0 = sk[base + j];
            const float tt = (xi - k0) * sid[base + j];
            const float c0 = sc[base + j];
            const float c1 = sc[base + j + 1];
            r[i] = fmaf(tt, c1 - c0, c0);
        }

        o4[2 * t]     = make_float4(r[0], r[1], r[2], r[3]);
        o4[2 * t + 1] = make_float4(r[4], r[5], r[6], r[7]);
    }
}

extern "C" void kernel_launch(void* const* d_in, const int* in_sizes, int n_in,
                              void* d_out, int out_size)
{
    const float* u     = (const float*)d_in[0];
    const float* knots = (const float*)d_in[1];
    const float* coefs = (const float*)d_in[2];
    float*       out   = (float*)d_out;

    const int n  = in_sizes[0];     // 67,108,864 (divisible by 8)
    const int n4 = n >> 2;

    // raise dynamic smem limit (host-side attr set; capture-safe, deterministic)
    static_assert(SMEM_BYTES <= 227 * 1024, "smem over sm_103a limit");
    cudaFuncSetAttribute(bspline_kernel,
                         cudaFuncAttributeMaxDynamicSharedMemorySize, SMEM_BYTES);

    int dev = 0, nsm = 148;
    cudaGetDevice(&dev);
    cudaDeviceGetAttribute(&nsm, cudaDevAttrMultiProcessorCount, dev);

    bspline_kernel<<<nsm, 1024, SMEM_BYTES>>>(u, knots, coefs, out, n4);
}

// round 3
// speedup vs baseline: 2.8230x; 2.8230x over previous
#include <cuda_runtime.h>

// BSplineLayer: piecewise-linear spline eval.
// u: [4096, 64, 256] f32 (flat, channel = i % 256)
// knots: [256, 64] sorted ascending per channel; coefs: [256, 64].
// out = c0 + (x-k0)/(k1-k0+1e-6) * (c1-c0), segment via searchsorted-left.
//
// Fast path (taken when knots are affine per channel, verified at runtime):
// index j = clamp(floor((x-k0)*invh), 0, 62) computed in registers; the only
// shared read per element is (c_j, dc_j) as one LDS.64.

#define M_CH    256
#define K_KNOTS 64
#define N_SEG   63
#define EPS     1e-6f

// smem: float4 sparam[256] | float2 sseg[256*64] | int flag
#define SMEM_BYTES (256 * 16 + 256 * 64 * 8 + 16)

__global__ __launch_bounds__(1024, 1)
void bspline_kernel(const float* __restrict__ u,
                    const float* __restrict__ knots,
                    const float* __restrict__ coefs,
                    float* __restrict__ out,
                    int n8 /* groups of 8 elements */)
{
    extern __shared__ char smem_raw[];
    float4* sparam = (float4*)smem_raw;                       // [256] (invh, b, scale, 0)
    float2* sseg   = (float2*)(smem_raw + 256 * 16);          // [256][64] (c_j, dc_j)
    int*    sflag  = (int*)(smem_raw + 256 * 16 + 256 * 64 * 8);

    const int tid = threadIdx.x;

    if (tid == 0) *sflag = 0;
    __syncthreads();

    // ---- stage coef segments: sseg[c*64+j] = (c_j, c_{j+1}-c_j) ----
    for (int i = tid; i < M_CH * K_KNOTS; i += blockDim.x) {
        int c = i >> 6;
        int j = i & 63;
        if (j < N_SEG) {
            float c0 = coefs[c * K_KNOTS + j];
            float c1 = coefs[c * K_KNOTS + j + 1];
            sseg[i] = make_float2(c0, c1 - c0);
        }
    }

    // ---- per-channel affine params + uniformity check ----
    if (tid < M_CH) {
        const int c = tid;
        const float* kc = knots + c * K_KNOTS;
        float k0 = kc[0];
        float kl = kc[K_KNOTS - 1];
        float h  = (kl - k0) * (1.0f / (float)N_SEG);
        float invh = (float)N_SEG / (kl - k0);
        float tol = 1e-4f * fabsf(h) + 1e-30f;
        bool bad = !(h > 0.0f);
        #pragma unroll 4
        for (int j = 1; j < K_KNOTS - 1; j++) {
            float pred = fmaf((float)j, h, k0);
            if (fabsf(kc[j] - pred) > tol) { bad = true; break; }
        }
        if (bad) *sflag = 1;
        float scale = h / (h + EPS);
        sparam[c] = make_float4(invh, -k0 * invh, scale, 0.0f);
    }
    __syncthreads();

    const bool affine = (*sflag == 0);

    const float4* __restrict__ u4 = (const float4*)u;
    float4*       __restrict__ o4 = (float4*)out;
    const int gtid   = blockIdx.x * blockDim.x + tid;
    const int stride = blockDim.x * gridDim.x;   // multiple of 32 -> cb loop-invariant
    const int cb     = (gtid * 8) & (M_CH - 1);

    if (affine) {
        // preload this thread's 8 channel params into registers
        float p_invh[8], p_b[8], p_scale[8];
        #pragma unroll
        for (int i = 0; i < 8; i++) {
            float4 p = sparam[cb + i];
            p_invh[i] = p.x; p_b[i] = p.y; p_scale[i] = p.z;
        }
        const float2* __restrict__ segbase = sseg + (cb << 6);

        for (int t = gtid; t < n8; t += stride) {
            float4 a = u4[2 * t];
            float4 b = u4[2 * t + 1];
            float x[8] = {a.x, a.y, a.z, a.w, b.x, b.y, b.z, b.w};
            float r[8];
            #pragma unroll
            for (int i = 0; i < 8; i++) {
                float s  = fmaf(x[i], p_invh[i], p_b[i]);
                float jf = floorf(s);
                jf = fminf(fmaxf(jf, 0.0f), (float)(N_SEG - 1));
                int  ji = (int)jf;
                float2 cd = segbase[(i << 6) + ji];       // ONE LDS.64 per element
                float tt = (s - jf) * p_scale[i];
                r[i] = fmaf(tt, cd.y, cd.x);
            }
            o4[2 * t]     = make_float4(r[0], r[1], r[2], r[3]);
            o4[2 * t + 1] = make_float4(r[4], r[5], r[6], r[7]);
        }
    } else {
        // generic fallback: exact searchsorted-left via binary search on global knots
        for (int t = gtid; t < n8; t += stride) {
            float4 a = u4[2 * t];
            float4 b = u4[2 * t + 1];
            float x[8] = {a.x, a.y, a.z, a.w, b.x, b.y, b.z, b.w};
            float r[8];
            #pragma unroll
            for (int i = 0; i < 8; i++) {
                const int c = cb + i;
                const float* kc = knots + c * K_KNOTS;
                const float xi = x[i];
                int lo = 0, hi = K_KNOTS;
                while (lo < hi) {
                    int mid = (lo + hi) >> 1;
                    if (__ldg(kc + mid) < xi) lo = mid + 1; else hi = mid;
                }
                int j = min(max(lo - 1, 0), N_SEG - 1);
                float k0 = __ldg(kc + j);
                float k1 = __ldg(kc + j + 1);
                float2 cd = sseg[(c << 6) + j];
                float tt = (xi - k0) / (k1 - k0 + EPS);
                r[i] = fmaf(tt, cd.y, cd.x);
            }
            o4[2 * t]     = make_float4(r[0], r[1], r[2], r[3]);
            o4[2 * t + 1] = make_float4(r[4], r[5], r[6], r[7]);
        }
    }
}

extern "C" void kernel_launch(void* const* d_in, const int* in_sizes, int n_in,
                              void* d_out, int out_size)
{
    const float* u     = (const float*)d_in[0];
    const float* knots = (const float*)d_in[1];
    const float* coefs = (const float*)d_in[2];
    float*       out   = (float*)d_out;

    const int n  = in_sizes[0];   // 67,108,864 (divisible by 8)
    const int n8 = n >> 3;

    static_assert(SMEM_BYTES <= 227 * 1024, "smem over sm_103a limit");
    cudaFuncSetAttribute(bspline_kernel,
                         cudaFuncAttributeMaxDynamicSharedMemorySize, SMEM_BYTES);

    int dev = 0, nsm = 148;
    cudaGetDevice(&dev);
    cudaDeviceGetAttribute(&nsm, cudaDevAttrMultiProcessorCount, dev);

    bspline_kernel<<<nsm, 1024, SMEM_BYTES>>>(u, knots, coefs, out, n8);
}